// round 11
// baseline (speedup 1.0000x reference)
#include <cuda_runtime.h>

// Input (B,H,W,C) = (16,128,128,128) fp32, factor (2,2) half-pixel bilinear
// upsample -> (16,256,256,128) fp32.
//
// R10 quad kernel (best: 6.33TB/s, traffic at the 640MB floor), with ONE
// change: default store policy instead of __stcs (evict-streaming). A/B test:
// .cs marks output lines evict-first, which may fragment L2->DRAM writeback
// bursts; the input reuse window (~3MB) is tiny vs L2 (126MB) so default
// write-allocate cannot meaningfully evict the read stream.
// One work item per thread: (b,qh,qw,c4) -> 4 tap loads, 4+ stores.

#define B_   16
#define H_   128
#define W_   128
#define C4_  32          // 128 channels / 4
#define OH_  256
#define OW_  256

#define NT_  128

__device__ __forceinline__ float4 lerp4(float4 v0, float4 v1, float t) {
    float4 r;
    r.x = fmaf(t, v1.x - v0.x, v0.x);
    r.y = fmaf(t, v1.y - v0.y, v0.y);
    r.z = fmaf(t, v1.z - v0.z, v0.z);
    r.w = fmaf(t, v1.w - v0.w, v0.w);
    return r;
}

__global__ __launch_bounds__(NT_) void upsample2x_quad_st(
    const float4* __restrict__ in, float4* __restrict__ out)
{
    int idx = blockIdx.x * NT_ + threadIdx.x;   // exactly B*128*128*32 threads
    int c4 = idx & (C4_ - 1);
    int qw = (idx >> 5) & (W_ - 1);
    int qh = (idx >> 12) & (H_ - 1);
    int b  = idx >> 19;

    int r1 = qh < H_ - 1 ? qh + 1 : H_ - 1;
    int c1 = qw < W_ - 1 ? qw + 1 : W_ - 1;

    const float4* base = in + (size_t)b * (H_ * W_ * C4_) + c4;
    float4 v00 = __ldg(base + (qh * W_ + qw) * C4_);
    float4 v01 = __ldg(base + (qh * W_ + c1) * C4_);
    float4 v10 = __ldg(base + (r1 * W_ + qw) * C4_);
    float4 v11 = __ldg(base + (r1 * W_ + c1) * C4_);

    // H interpolation first (matches reference order).
    float4 a0 = lerp4(v00, v10, 0.25f);
    float4 a1 = lerp4(v01, v11, 0.25f);
    float4 b0 = lerp4(v00, v10, 0.75f);
    float4 b1 = lerp4(v01, v11, 0.75f);

    float4* obase = out + (size_t)b * (OH_ * OW_ * C4_) + c4;
    int rowA = 2 * qh + 1;
    int colA = 2 * qw + 1;

    float4* oA = obase + (size_t)rowA * (OW_ * C4_);
    oA[colA * C4_] = lerp4(a0, a1, 0.25f);
    if (qw < W_ - 1)
        oA[(colA + 1) * C4_] = lerp4(a0, a1, 0.75f);
    if (qh < H_ - 1) {
        float4* oB = oA + OW_ * C4_;
        oB[colA * C4_] = lerp4(b0, b1, 0.25f);
        if (qw < W_ - 1)
            oB[(colA + 1) * C4_] = lerp4(b0, b1, 0.75f);
    }

    // Output row 0 = source row 0 (h-frac collapses), w-interp as usual.
    if (qh == 0) {
        obase[colA * C4_] = lerp4(v00, v01, 0.25f);
        if (qw < W_ - 1)
            obase[(colA + 1) * C4_] = lerp4(v00, v01, 0.75f);
        if (qw == 0)
            obase[0] = v00;                     // (0,0) corner
    }

    // Output col 0 = source col 0 (w-frac collapses): values a0 / b0.
    if (qw == 0) {
        obase[(size_t)rowA * (OW_ * C4_)] = a0;
        if (qh < H_ - 1)
            obase[(size_t)(rowA + 1) * (OW_ * C4_)] = b0;
    }
}

extern "C" void kernel_launch(void* const* d_in, const int* in_sizes, int n_in,
                              void* d_out, int out_size) {
    const float4* in = (const float4*)d_in[0];
    float4* out = (float4*)d_out;
    int total = B_ * H_ * W_ * C4_;    // 8,388,608 threads
    upsample2x_quad_st<<<total / NT_, NT_>>>(in, out);
}

// round 13
// speedup vs baseline: 1.0103x; 1.0103x over previous
#include <cuda_runtime.h>

// Input (B,H,W,C) = (16,128,128,128) fp32, factor (2,2) half-pixel bilinear
// upsample -> (16,256,256,128) fp32.
//
// Quad kernel (best form: 6.36TB/s, DRAM traffic at the 640MB floor).
// Final A/B: __stwt (write-through, no L2 dirty allocate) on output stores.
// Output is write-once-never-read; .wt removes 512MB of dirty-line lifecycle
// from L2 and exposes the write stream to the MC directly instead of via
// eviction-driven writeback bursts. Reads unchanged.
// One work item per thread: (b,qh,qw,c4) -> 4 tap loads, 4+ stores; each
// warp's store covers a contiguous 512B segment (full lines, coalesced).

#define B_   16
#define H_   128
#define W_   128
#define C4_  32          // 128 channels / 4
#define OH_  256
#define OW_  256

#define NT_  128

__device__ __forceinline__ float4 lerp4(float4 v0, float4 v1, float t) {
    float4 r;
    r.x = fmaf(t, v1.x - v0.x, v0.x);
    r.y = fmaf(t, v1.y - v0.y, v0.y);
    r.z = fmaf(t, v1.z - v0.z, v0.z);
    r.w = fmaf(t, v1.w - v0.w, v0.w);
    return r;
}

__global__ __launch_bounds__(NT_) void upsample2x_quad_wt(
    const float4* __restrict__ in, float4* __restrict__ out)
{
    int idx = blockIdx.x * NT_ + threadIdx.x;   // exactly B*128*128*32 threads
    int c4 = idx & (C4_ - 1);
    int qw = (idx >> 5) & (W_ - 1);
    int qh = (idx >> 12) & (H_ - 1);
    int b  = idx >> 19;

    int r1 = qh < H_ - 1 ? qh + 1 : H_ - 1;
    int c1 = qw < W_ - 1 ? qw + 1 : W_ - 1;

    const float4* base = in + (size_t)b * (H_ * W_ * C4_) + c4;
    float4 v00 = __ldg(base + (qh * W_ + qw) * C4_);
    float4 v01 = __ldg(base + (qh * W_ + c1) * C4_);
    float4 v10 = __ldg(base + (r1 * W_ + qw) * C4_);
    float4 v11 = __ldg(base + (r1 * W_ + c1) * C4_);

    // H interpolation first (matches reference order).
    float4 a0 = lerp4(v00, v10, 0.25f);
    float4 a1 = lerp4(v01, v11, 0.25f);
    float4 b0 = lerp4(v00, v10, 0.75f);
    float4 b1 = lerp4(v01, v11, 0.75f);

    float4* obase = out + (size_t)b * (OH_ * OW_ * C4_) + c4;
    int rowA = 2 * qh + 1;
    int colA = 2 * qw + 1;

    float4* oA = obase + (size_t)rowA * (OW_ * C4_);
    __stwt(oA + colA * C4_, lerp4(a0, a1, 0.25f));
    if (qw < W_ - 1)
        __stwt(oA + (colA + 1) * C4_, lerp4(a0, a1, 0.75f));
    if (qh < H_ - 1) {
        float4* oB = oA + OW_ * C4_;
        __stwt(oB + colA * C4_, lerp4(b0, b1, 0.25f));
        if (qw < W_ - 1)
            __stwt(oB + (colA + 1) * C4_, lerp4(b0, b1, 0.75f));
    }

    // Output row 0 = source row 0 (h-frac collapses), w-interp as usual.
    if (qh == 0) {
        __stwt(obase + colA * C4_, lerp4(v00, v01, 0.25f));
        if (qw < W_ - 1)
            __stwt(obase + (colA + 1) * C4_, lerp4(v00, v01, 0.75f));
        if (qw == 0)
            __stwt(obase, v00);                 // (0,0) corner
    }

    // Output col 0 = source col 0 (w-frac collapses): values a0 / b0.
    if (qw == 0) {
        __stwt(obase + (size_t)rowA * (OW_ * C4_), a0);
        if (qh < H_ - 1)
            __stwt(obase + (size_t)(rowA + 1) * (OW_ * C4_), b0);
    }
}

extern "C" void kernel_launch(void* const* d_in, const int* in_sizes, int n_in,
                              void* d_out, int out_size) {
    const float4* in = (const float4*)d_in[0];
    float4* out = (float4*)d_out;
    int total = B_ * H_ * W_ * C4_;    // 8,388,608 threads
    upsample2x_quad_wt<<<total / NT_, NT_>>>(in, out);
}